// round 8
// baseline (speedup 1.0000x reference)
#include <cuda_runtime.h>
#include <cuda_bf16.h>
#include <math.h>

#define Nn 64
#define Cc 512
#define Tt 512
#define Kk 1024
#define NCT (Nn*Cc*Tt)

#define GCHUNK 8                // K' = 512 bf16 (h.h only) = 8 chunks of 64
#define CHUNK_BYTES 16384       // 128 rows x 64 bf16 (SW128-swizzled)
#define PANEL_BYTES (GCHUNK*CHUNK_BYTES)   // 128 KB
#define PANEL_ELEMS (GCHUNK*8192)

typedef unsigned int u32;
typedef unsigned long long u64;

// ---------------- device scratch ------------------------------------------
__device__ float  g_xt[NCT];                             // x in (N,T,C)
__device__ float  g_rd[32768 * Cc];                      // pooled rows fp32
__device__ __nv_bfloat16 g_scoreb[32768 * Kk];           // pass-1 scores (bf16)
__device__ __align__(16) __nv_bfloat16 g_rdS[256 * PANEL_ELEMS]; // h split A
__device__ __align__(16) __nv_bfloat16 g_cbS[8   * PANEL_ELEMS]; // h split B
__device__ int    g_idx[Nn*(128+256+512)];
__device__ float  g_cbhalf[Kk];
__device__ float  g_hn[32768];   // ||h_x|| per row
__device__ float  g_ex[32768];   // ||x - h_x|| per row
__device__ float  g_Hy, g_Ey;    // max ||h_k||, max ||cb_k - h_k||
__device__ float  g_hist[Kk];
__device__ double g_err[3];
__device__ float  g_masksum;

// ---------------- PTX helpers ---------------------------------------------
__device__ __forceinline__ u32 smem_u32(const void* p) {
    u32 a;
    asm("{ .reg .u64 t; cvta.to.shared.u64 t, %1; cvt.u32.u64 %0, t; }" : "=r"(a) : "l"(p));
    return a;
}
__device__ __forceinline__ void cpa16s(u32 dst, const void* src) {
    asm volatile("cp.async.cg.shared.global [%0], [%1], 16;" :: "r"(dst), "l"(src));
}
#define CP_COMMIT() asm volatile("cp.async.commit_group;" ::: "memory")
#define CP_WAIT(n)  asm volatile("cp.async.wait_group %0;" :: "n"(n) : "memory")

#define LDSM4(r0, r1, r2, r3, a) \
    asm volatile("ldmatrix.sync.aligned.m8n8.x4.shared.b16 {%0,%1,%2,%3}, [%4];" \
                 : "=r"(r0), "=r"(r1), "=r"(r2), "=r"(r3) : "r"(a))

#define MMA16816(c, a, b) \
    asm volatile("mma.sync.aligned.m16n8k16.row.col.f32.bf16.bf16.f32 " \
                 "{%0,%1,%2,%3}, {%4,%5,%6,%7}, {%8,%9}, {%0,%1,%2,%3};" \
                 : "+f"((c)[0]), "+f"((c)[1]), "+f"((c)[2]), "+f"((c)[3]) \
                 : "r"((a)[0]), "r"((a)[1]), "r"((a)[2]), "r"((a)[3]), \
                   "r"((b)[0]), "r"((b)[1]))

__device__ __forceinline__ u32 swoff(int r, int kb) {
    u32 off = ((u32)(r >> 3) << 10) + ((u32)(r & 7) << 7) + (u32)kb;
    return off ^ ((off >> 3) & 0x70);
}
__device__ __forceinline__ void atomicMaxF(float* a, float v) {
    atomicMax((int*)a, __float_as_int(v));   // valid: values >= 0
}

// ---------------- transpose in: x (N,C,T) -> g_xt (N,T,C) -------------------
__global__ void k_transpose_in(const float* __restrict__ x) {
    __shared__ float tile[32][33];
    int n = blockIdx.z, t0 = blockIdx.x * 32, c0 = blockIdx.y * 32;
    const float* xin = x + (size_t)n * Cc * Tt;
#pragma unroll
    for (int k = 0; k < 4; k++)
        tile[threadIdx.y + k * 8][threadIdx.x] =
            xin[(size_t)(c0 + threadIdx.y + k * 8) * Tt + t0 + threadIdx.x];
    __syncthreads();
    float* xo = g_xt + (size_t)n * Tt * Cc;
#pragma unroll
    for (int k = 0; k < 4; k++) {
        int t = t0 + threadIdx.y + k * 8;
        xo[(size_t)t * Cc + c0 + threadIdx.x] = tile[threadIdx.x][threadIdx.y + k * 8];
    }
}

// ------- codebook: half norms + bound constants ----------------------------
__global__ void k_cbhalf(const float* __restrict__ cb) {
    int k = blockIdx.x;
    const float* row = cb + (size_t)k * Cc;
    float s = 0.f, h2 = 0.f, e2 = 0.f;
    for (int i = threadIdx.x; i < Cc; i += 128) {
        float v = row[i];
        float hf = __bfloat162float(__float2bfloat16(v));
        float d = v - hf;
        s += v * v; h2 += hf * hf; e2 += d * d;
    }
#pragma unroll
    for (int o = 16; o; o >>= 1) {
        s  += __shfl_down_sync(0xffffffffu, s,  o);
        h2 += __shfl_down_sync(0xffffffffu, h2, o);
        e2 += __shfl_down_sync(0xffffffffu, e2, o);
    }
    __shared__ float ws[4], wh[4], we[4];
    if ((threadIdx.x & 31) == 0) {
        ws[threadIdx.x >> 5] = s; wh[threadIdx.x >> 5] = h2; we[threadIdx.x >> 5] = e2;
    }
    __syncthreads();
    if (threadIdx.x == 0) {
        float S = ws[0] + ws[1] + ws[2] + ws[3];
        float H = wh[0] + wh[1] + wh[2] + wh[3];
        float E = we[0] + we[1] + we[2] + we[3];
        g_cbhalf[k] = 0.5f * S;
        atomicMaxF(&g_Hy, sqrtf(H));
        atomicMaxF(&g_Ey, sqrtf(E));
    }
}

// ---------------- codebook h-split panels -----------------------------------
__global__ void k_cb_split(const float* __restrict__ cb) {
    int panel = blockIdx.x;
    for (int it = 0; it < 32; it++) {
        int item = it * 256 + threadIdx.x;
        int r = item >> 6, kg = item & 63;
        const float4* s4 = (const float4*)(cb + ((size_t)(panel * 128 + r)) * Cc + kg * 8);
        float4 a = s4[0], b = s4[1];
        float f[8] = {a.x, a.y, a.z, a.w, b.x, b.y, b.z, b.w};
        union { __nv_bfloat16 bb[8]; uint4 v; } H;
#pragma unroll
        for (int j = 0; j < 8; j++) H.bb[j] = __float2bfloat16(f[j]);
        u32 sw = swoff(r, (kg & 7) << 4);
        char* pb = (char*)g_cbS + (size_t)panel * PANEL_BYTES
                 + (size_t)(kg >> 3) * CHUNK_BYTES + sw;
        *(uint4*)pb = H.v;
    }
}

// ---------------- scalar prep ----------------------------------------------
__global__ void k_prep_scalars(const int* __restrict__ m_lens) {
    __shared__ int sm[Nn];
    if (threadIdx.x < Nn) sm[threadIdx.x] = m_lens[threadIdx.x];
    __syncthreads();
    if (threadIdx.x == 0) {
        int s = 0;
        for (int i = 0; i < Nn; i++) s += sm[i];
        g_masksum = (float)s;
        g_Hy = 0.f; g_Ey = 0.f;
    }
    if (threadIdx.x < 3) g_err[threadIdx.x] = 0.0;
}
__global__ void k_reset_hist() { g_hist[blockIdx.x * 256 + threadIdx.x] = 0.f; }

// ------- upsample helper: subtract up(j) for 8 channels ----------------------
__device__ __forceinline__ void sub_up8(float* acc, const float* __restrict__ cb,
                                        const int* __restrict__ idxn,
                                        int j, int s_up, int t_up, int tlim, int kgc) {
    float pos = (j + 0.5f) / (float)s_up - 0.5f;
    pos = fminf(fmaxf(pos, 0.0f), (float)(t_up - 1));
    int lo = (int)floorf(pos);
    int hi = min(lo + 1, t_up - 1);
    float w = pos - (float)lo;
    int ilo = (lo < tlim) ? idxn[lo] : -1;
    int ihi = (hi < tlim) ? idxn[hi] : -1;
    float wl = 1.0f - w, wh = w;
    if (ilo >= 0) {
        const float4* p = (const float4*)(cb + (size_t)ilo * Cc + kgc);
        float4 a = p[0], b = p[1];
        acc[0] -= wl * a.x; acc[1] -= wl * a.y; acc[2] -= wl * a.z; acc[3] -= wl * a.w;
        acc[4] -= wl * b.x; acc[5] -= wl * b.y; acc[6] -= wl * b.z; acc[7] -= wl * b.w;
    }
    if (ihi >= 0) {
        const float4* p = (const float4*)(cb + (size_t)ihi * Cc + kgc);
        float4 a = p[0], b = p[1];
        acc[0] -= wh * a.x; acc[1] -= wh * a.y; acc[2] -= wh * a.z; acc[3] -= wh * a.w;
        acc[4] -= wh * b.x; acc[5] -= wh * b.y; acc[6] -= wh * b.z; acc[7] -= wh * b.w;
    }
}

// ------- pooled residual: rd = pool_s(mask * (x - up4 - up2)) ----------------
__global__ void k_pool(const float* __restrict__ cb, const int* __restrict__ m_lens,
                       int s, int t, int stage,
                       const int* __restrict__ idx4, const int* __restrict__ idx2) {
    __shared__ float s_h2[128], s_e2[128];
    int tid = threadIdx.x, panel = blockIdx.x;
    if (tid < 128) { s_h2[tid] = 0.f; s_e2[tid] = 0.f; }
    __syncthreads();
    float inv = 1.0f / (float)s;
    for (int it = 0; it < 32; it++) {
        int item = it * 256 + tid;
        int r = item >> 6, kg = item & 63;
        int kgc = kg * 8;
        int grow = panel * 128 + r;
        int n = grow / t, tp = grow % t;
        int ml = m_lens[n];
        const int* idx4n = idx4 + n * 128;
        const int* idx2n = idx2 + n * 256;
        int tlim4 = ml >> 2, tlim2 = ml >> 1;
        float f[8] = {0.f, 0.f, 0.f, 0.f, 0.f, 0.f, 0.f, 0.f};
        for (int u = 0; u < s; u++) {
            int j = tp * s + u;
            if (j < ml) {
                const float4* s4 =
                    (const float4*)(g_xt + ((size_t)n * Tt + j) * Cc + kgc);
                float4 a = s4[0], b = s4[1];
                float acc[8] = {a.x, a.y, a.z, a.w, b.x, b.y, b.z, b.w};
                if (stage >= 1) sub_up8(acc, cb, idx4n, j, 4, 128, tlim4, kgc);
                if (stage >= 2) sub_up8(acc, cb, idx2n, j, 2, 256, tlim2, kgc);
#pragma unroll
                for (int q = 0; q < 8; q++) f[q] += acc[q];
            }
        }
#pragma unroll
        for (int q = 0; q < 8; q++) f[q] *= inv;
        float4* rp = (float4*)(g_rd + (size_t)grow * Cc + kgc);
        rp[0] = make_float4(f[0], f[1], f[2], f[3]);
        rp[1] = make_float4(f[4], f[5], f[6], f[7]);
        union { __nv_bfloat16 bb[8]; uint4 v; } H;
        float h2 = 0.f, e2 = 0.f;
#pragma unroll
        for (int q = 0; q < 8; q++) {
            __nv_bfloat16 h = __float2bfloat16(f[q]);
            float hf = __bfloat162float(h);
            float d = f[q] - hf;
            H.bb[q] = h; h2 += hf * hf; e2 += d * d;
        }
        u32 sw = swoff(r, (kg & 7) << 4);
        char* pb = (char*)g_rdS + (size_t)panel * PANEL_BYTES
                 + (size_t)(kg >> 3) * CHUNK_BYTES + sw;
        *(uint4*)pb = H.v;
#pragma unroll
        for (int o = 16; o; o >>= 1) {
            h2 += __shfl_down_sync(0xffffffffu, h2, o);
            e2 += __shfl_down_sync(0xffffffffu, e2, o);
        }
        if ((tid & 31) == 0) {
            atomicAdd(&s_h2[r], h2);
            atomicAdd(&s_e2[r], e2);
        }
    }
    __syncthreads();
    if (tid < 128) {
        g_hn[panel * 128 + tid] = sqrtf(s_h2[tid]);
        g_ex[panel * 128 + tid] = sqrtf(s_e2[tid]);
    }
}

// ---------------- pass 1: h.h GEMM -> bf16 scores ----------------------------
__device__ __forceinline__ void fill_stage(u32 stage, const char* A,
                                           const char* B, int tid) {
#pragma unroll
    for (int q = 0; q < 4; q++) {
        int off = (tid + q * 256) * 16;
        cpa16s(stage + off, A + off);
    }
#pragma unroll
    for (int q = 0; q < 4; q++) {
        int off = (tid + q * 256) * 16;
        cpa16s(stage + CHUNK_BYTES + off, B + off);
    }
    CP_COMMIT();
}

__global__ void __launch_bounds__(256, 2)
k_quantize6(const int* __restrict__ m_lens, int t, int scale,
            __nv_bfloat16* __restrict__ score) {
    extern __shared__ char dsm[];
    __shared__ float s_cbh[128];

    int tid = threadIdx.x, wid = tid >> 5, lane = tid & 31;
    int mbase = blockIdx.y * 128;
    int n = mbase / t;
    int tlim = m_lens[n] / scale;
    if (mbase % t >= tlim) return;           // fully masked panel

    u32 dbase = (smem_u32(dsm) + 1023) & ~1023u;
    u32 st0 = dbase, st1 = dbase + 2 * CHUNK_BYTES;

    if (tid < 128) s_cbh[tid] = g_cbhalf[blockIdx.x * 128 + tid];

    const char* A = (const char*)g_rdS + (size_t)blockIdx.y * PANEL_BYTES;
    const char* B = (const char*)g_cbS + (size_t)blockIdx.x * PANEL_BYTES;

    fill_stage(st0, A, B, tid);
    fill_stage(st1, A + CHUNK_BYTES, B + CHUNK_BYTES, tid);

    int warp_m = wid >> 2, warp_n = wid & 3;
    int sub = lane >> 3;
    int a_row = warp_m * 64 + (lane & 7) + ((sub & 1) << 3);
    int a_kb  = (sub >> 1) << 4;
    int b_row = warp_n * 32 + (lane & 7) + ((lane >> 4) << 3);
    int b_kb  = ((lane >> 3) & 1) << 4;

    float acc[4][4][4];
#pragma unroll
    for (int i = 0; i < 4; i++)
#pragma unroll
        for (int j = 0; j < 4; j++)
#pragma unroll
            for (int q = 0; q < 4; q++) acc[i][j][q] = 0.f;

    for (int i = 0; i < GCHUNK; i++) {
        if (i < GCHUNK - 1) CP_WAIT(1); else CP_WAIT(0);
        __syncthreads();
        u32 sa = (i & 1) ? st1 : st0;
        u32 sb = sa + CHUNK_BYTES;
#pragma unroll
        for (int ks = 0; ks < 4; ks++) {
            u32 af[4][4];
#pragma unroll
            for (int mt = 0; mt < 4; mt++) {
                u32 addr = sa + swoff(a_row + mt * 16, ks * 32 + a_kb);
                LDSM4(af[mt][0], af[mt][1], af[mt][2], af[mt][3], addr);
            }
            u32 bf[4][2];
#pragma unroll
            for (int pr = 0; pr < 2; pr++) {
                u32 addr = sb + swoff(b_row + pr * 16, ks * 32 + b_kb);
                LDSM4(bf[2 * pr][0], bf[2 * pr][1],
                      bf[2 * pr + 1][0], bf[2 * pr + 1][1], addr);
            }
#pragma unroll
            for (int mt = 0; mt < 4; mt++)
#pragma unroll
                for (int nt = 0; nt < 4; nt++)
                    MMA16816(acc[mt][nt], af[mt], bf[nt]);
        }
        __syncthreads();
        if (i + 2 < GCHUNK)
            fill_stage((i & 1) ? st1 : st0,
                       A + (size_t)(i + 2) * CHUNK_BYTES,
                       B + (size_t)(i + 2) * CHUNK_BYTES, tid);
    }

    int r0 = warp_m * 64 + (lane >> 2);
    int cbase = warp_n * 32 + (lane & 3) * 2;
#pragma unroll
    for (int mt = 0; mt < 4; mt++) {
#pragma unroll
        for (int nt = 0; nt < 4; nt++) {
            int cl = cbase + nt * 8;
            float h0 = s_cbh[cl], h1 = s_cbh[cl + 1];
            size_t coff = (size_t)blockIdx.x * 128 + cl;
            int grow0 = mbase + r0 + mt * 16;
            *(__nv_bfloat162*)(score + (size_t)grow0 * Kk + coff) =
                __floats2bfloat162_rn(acc[mt][nt][0] - h0, acc[mt][nt][1] - h1);
            *(__nv_bfloat162*)(score + (size_t)(grow0 + 8) * Kk + coff) =
                __floats2bfloat162_rn(acc[mt][nt][2] - h0, acc[mt][nt][3] - h1);
        }
    }
}

// ---------------- rescore: prune + exact fp32 argmax + hist ------------------
__global__ void k_rescore(const float* __restrict__ cb,
                          const int* __restrict__ m_lens,
                          int t, int scale, int* __restrict__ idx_out) {
    int wid = threadIdx.x >> 5, lane = threadIdx.x & 31;
    int row = blockIdx.x * 8 + wid;
    int n = row / t, tr = row % t;
    int tlim = m_lens[n] / scale;
    if (tr >= tlim) {
        if (lane == 0) idx_out[row] = 0;
        return;
    }

    float xr[16];
    const float* xrp = g_rd + (size_t)row * Cc;
#pragma unroll
    for (int c = 0; c < 16; c++) xr[c] = xrp[c * 32 + lane];

    u32 sc[16];
    const u32* su = (const u32*)(g_scoreb + (size_t)row * Kk);
#pragma unroll
    for (int j = 0; j < 16; j++) sc[j] = su[j * 32 + lane];

    float mx = -1e30f;
#pragma unroll
    for (int j = 0; j < 16; j++) {
        float s0 = __uint_as_float(sc[j] << 16);
        float s1 = __uint_as_float(sc[j] & 0xffff0000u);
        mx = fmaxf(mx, fmaxf(s0, s1));
    }
#pragma unroll
    for (int o = 16; o; o >>= 1) mx = fmaxf(mx, __shfl_xor_sync(0xffffffffu, mx, o));

    float B = 1.02f * (g_hn[row] * g_Ey + g_ex[row] * (g_Hy + g_Ey)) + 1e-2f;
    float eps = 0.004f * (fabsf(mx) + 2.0f * B) + 1e-2f;   // bf16 rounding margin
    float tau = mx - 2.0f * B - 2.0f * eps;

    float best = -1e30f; int bi = 0;
    for (int j = 0; j < 16; j++) {
        float s0 = __uint_as_float(sc[j] << 16);
        float s1 = __uint_as_float(sc[j] & 0xffff0000u);
        unsigned m = __ballot_sync(0xffffffffu, (s0 >= tau) || (s1 >= tau));
        while (m) {
            int l = __ffs(m) - 1; m &= m - 1;
            u32 uv = __shfl_sync(0xffffffffu, sc[j], l);
            float t0 = __uint_as_float(uv << 16);
            float t1 = __uint_as_float(uv & 0xffff0000u);
            int k0 = (j * 32 + l) * 2;
#pragma unroll
            for (int h = 0; h < 2; h++) {
                float sv_b = h ? t1 : t0;
                if (sv_b < tau) continue;
                int k = k0 + h;
                const float* cbk = cb + (size_t)k * Cc;
                float p = 0.f;
#pragma unroll
                for (int c = 0; c < 16; c++) p = fmaf(xr[c], cbk[c * 32 + lane], p);
#pragma unroll
                for (int o = 16; o; o >>= 1) p += __shfl_xor_sync(0xffffffffu, p, o);
                float sv = p - g_cbhalf[k];
                if (sv > best) { best = sv; bi = k; }   // ascending k: first max wins
            }
        }
    }
    if (lane == 0) {
        idx_out[row] = bi;
        atomicAdd(&g_hist[bi], 1.0f);
    }
}

// ------- fused output: f_hat -> out (N,C,T) + all three loss terms ----------
__device__ __forceinline__ float up_1c(const float* __restrict__ cb,
                                       const int* __restrict__ idxn,
                                       int j, int s_up, int t_up, int tlim, int c) {
    float pos = (j + 0.5f) / (float)s_up - 0.5f;
    pos = fminf(fmaxf(pos, 0.0f), (float)(t_up - 1));
    int lo = (int)floorf(pos);
    int hi = min(lo + 1, t_up - 1);
    float w = pos - (float)lo;
    int ilo = (lo < tlim) ? idxn[lo] : -1;
    int ihi = (hi < tlim) ? idxn[hi] : -1;
    float r = 0.f;
    if (ilo >= 0) r += (1.0f - w) * cb[(size_t)ilo * Cc + c];
    if (ihi >= 0) r += w * cb[(size_t)ihi * Cc + c];
    return r;
}

__global__ void k_out(const float* __restrict__ cb, const int* __restrict__ m_lens,
                      const int* __restrict__ idx4, const int* __restrict__ idx2,
                      const int* __restrict__ idx1, float* __restrict__ out) {
    __shared__ float tile[32][33];
    __shared__ float ws[8];
    int n = blockIdx.z, t0 = blockIdx.x * 32, c0 = blockIdx.y * 32;
    int tx = threadIdx.x, ty = threadIdx.y;
    int ml = m_lens[n];
    const int* i4 = idx4 + n * 128;
    const int* i2 = idx2 + n * 256;
    const int* i1 = idx1 + n * 512;
    int c = c0 + tx;

    float lacc = 0.f;
#pragma unroll
    for (int k = 0; k < 4; k++) {
        int t = t0 + ty + k * 8;
        float f1 = up_1c(cb, i4, t, 4, 128, ml >> 2, c);
        float f2 = f1 + up_1c(cb, i2, t, 2, 256, ml >> 1, c);
        float f3 = f2 + up_1c(cb, i1, t, 1, 512, ml, c);
        tile[tx][ty + k * 8] = f3;
        if (t < ml) {
            float xv = g_xt[((size_t)n * Tt + t) * Cc + c];
            float e1 = xv - f1, e2 = xv - f2, e3 = xv - f3;
            lacc += e1 * e1 + e2 * e2 + e3 * e3;
        }
    }
#pragma unroll
    for (int o = 16; o; o >>= 1) lacc += __shfl_down_sync(0xffffffffu, lacc, o);
    int wid = (ty * 32 + tx) >> 5;
    if (((ty * 32 + tx) & 31) == 0) ws[wid] = lacc;
    __syncthreads();
    if (ty == 0 && tx == 0) {
        float s = 0.f;
        for (int q = 0; q < 8; q++) s += ws[q];
        atomicAdd(&g_err[0], (double)s);
    }
    float* oo = out + (size_t)n * Cc * Tt;
#pragma unroll
    for (int k = 0; k < 4; k++) {
        int cw = c0 + ty + k * 8;
        oo[(size_t)cw * Tt + t0 + tx] = tile[ty + k * 8][tx];
    }
}

// ---------------- finalize ---------------------------------------------------
__global__ void k_finalize(float* __restrict__ out) {
    int tid = threadIdx.x;
    float c = g_hist[tid];
    __shared__ float ws[32];
    float v = c;
#pragma unroll
    for (int o = 16; o; o >>= 1) v += __shfl_down_sync(0xffffffffu, v, o);
    if ((tid & 31) == 0) ws[tid >> 5] = v;
    __syncthreads();
    if (tid < 32) {
        float z = ws[tid];
#pragma unroll
        for (int o = 16; o; o >>= 1) z += __shfl_down_sync(0xffffffffu, z, o);
        if (tid == 0) ws[0] = z;
    }
    __syncthreads();
    float total = ws[0];
    __syncthreads();
    float p = c / total;
    float e = p * logf(p + 1e-7f);
#pragma unroll
    for (int o = 16; o; o >>= 1) e += __shfl_down_sync(0xffffffffu, e, o);
    if ((tid & 31) == 0) ws[tid >> 5] = e;
    __syncthreads();
    if (tid == 0) {
        float ent = 0.f;
        for (int i = 0; i < 32; i++) ent += ws[i];
        double denom = (double)g_masksum * (double)Tt;
        double loss = (g_err[0] + g_err[1] + g_err[2]) / denom / 3.0;
        out[NCT]     = (float)loss;
        out[NCT + 1] = expf(-ent);
    }
}

// ---------------- launch ------------------------------------------------------
extern "C" void kernel_launch(void* const* d_in, const int* in_sizes, int n_in,
                              void* d_out, int out_size) {
    const float* x = nullptr; const float* cb = nullptr; const int* m_lens = nullptr;
    for (int i = 0; i < n_in; i++) {
        if (in_sizes[i] == NCT)            x = (const float*)d_in[i];
        else if (in_sizes[i] == Kk * Cc)   cb = (const float*)d_in[i];
        else if (in_sizes[i] == Nn)        m_lens = (const int*)d_in[i];
    }
    float* out = (float*)d_out;

    const int DYN = 1024 + 4 * CHUNK_BYTES;
    cudaFuncSetAttribute(k_quantize6, cudaFuncAttributeMaxDynamicSharedMemorySize, DYN);

    void* idxv = nullptr; cudaGetSymbolAddress(&idxv, g_idx);
    int* idxbase = (int*)idxv;
    void* scv = nullptr;  cudaGetSymbolAddress(&scv, g_scoreb);
    __nv_bfloat16* score = (__nv_bfloat16*)scv;

    int* idx4 = idxbase;
    int* idx2 = idxbase + Nn * 128;
    int* idx1 = idxbase + Nn * 128 + Nn * 256;
    int* idxs[3] = {idx4, idx2, idx1};

    k_reset_hist<<<4, 256>>>();
    k_prep_scalars<<<1, 64>>>(m_lens);
    k_cbhalf<<<Kk, 128>>>(cb);
    k_cb_split<<<8, 256>>>(cb);
    {
        dim3 gb(Tt / 32, Cc / 32, Nn), tb(32, 8);
        k_transpose_in<<<gb, tb>>>(x);
    }

    const int scales[3] = {4, 2, 1};
    for (int s = 0; s < 3; s++) {
        int sc = scales[s], t = Tt / sc, M = Nn * t;
        int panels = M / 128;
        k_pool<<<panels, 256>>>(cb, m_lens, sc, t, s, idx4, idx2);
        k_quantize6<<<dim3(8, panels), 256, DYN>>>(m_lens, t, sc, score);
        k_rescore<<<M / 8, 256>>>(cb, m_lens, t, sc, idxs[s]);
    }

    {
        dim3 gb(Tt / 32, Cc / 32, Nn), tb(32, 8);
        k_out<<<gb, tb>>>(cb, m_lens, idx4, idx2, idx1, out);
    }
    k_finalize<<<1, 1024>>>(out);
}

// round 9
// speedup vs baseline: 1.0932x; 1.0932x over previous
#include <cuda_runtime.h>
#include <cuda_bf16.h>
#include <math.h>

#define Nn 64
#define Cc 512
#define Tt 512
#define Kk 1024
#define NCT (Nn*Cc*Tt)

#define GCHUNK 8                // K' = 512 bf16 (h.h only) = 8 chunks of 64
#define CHUNK_BYTES 16384       // 128 rows x 64 bf16 (SW128-swizzled)
#define PANEL_BYTES (GCHUNK*CHUNK_BYTES)   // 128 KB
#define PANEL_ELEMS (GCHUNK*8192)

typedef unsigned int u32;
typedef unsigned long long u64;

// ---------------- device scratch ------------------------------------------
__device__ float  g_xt[NCT];                             // x in (N,T,C)
__device__ float  g_fhat[NCT];                           // f_hat (N,T,C)
__device__ float  g_rd[32768 * Cc];                      // pooled rows fp32
__device__ __nv_bfloat16 g_scoreb[32768 * Kk];           // pass-1 scores (bf16)
__device__ __align__(16) __nv_bfloat16 g_rdS[256 * PANEL_ELEMS]; // h split A
__device__ __align__(16) __nv_bfloat16 g_cbS[8   * PANEL_ELEMS]; // h split B
__device__ int    g_idx[Nn*(128+256+512)];
__device__ float  g_cbhalf[Kk];
__device__ float  g_hn[32768];   // ||h_x|| per row
__device__ float  g_ex[32768];   // ||x - h_x|| per row
__device__ float  g_Hy, g_Ey;    // max ||h_k||, max ||cb_k - h_k||
__device__ float  g_hist[Kk];
__device__ double g_err[3];
__device__ float  g_masksum;

// ---------------- PTX helpers ---------------------------------------------
__device__ __forceinline__ u32 smem_u32(const void* p) {
    u32 a;
    asm("{ .reg .u64 t; cvta.to.shared.u64 t, %1; cvt.u32.u64 %0, t; }" : "=r"(a) : "l"(p));
    return a;
}
__device__ __forceinline__ void cpa16s(u32 dst, const void* src) {
    asm volatile("cp.async.cg.shared.global [%0], [%1], 16;" :: "r"(dst), "l"(src));
}
#define CP_COMMIT() asm volatile("cp.async.commit_group;" ::: "memory")
#define CP_WAIT(n)  asm volatile("cp.async.wait_group %0;" :: "n"(n) : "memory")

#define LDSM4(r0, r1, r2, r3, a) \
    asm volatile("ldmatrix.sync.aligned.m8n8.x4.shared.b16 {%0,%1,%2,%3}, [%4];" \
                 : "=r"(r0), "=r"(r1), "=r"(r2), "=r"(r3) : "r"(a))

#define MMA16816(c, a, b) \
    asm volatile("mma.sync.aligned.m16n8k16.row.col.f32.bf16.bf16.f32 " \
                 "{%0,%1,%2,%3}, {%4,%5,%6,%7}, {%8,%9}, {%0,%1,%2,%3};" \
                 : "+f"((c)[0]), "+f"((c)[1]), "+f"((c)[2]), "+f"((c)[3]) \
                 : "r"((a)[0]), "r"((a)[1]), "r"((a)[2]), "r"((a)[3]), \
                   "r"((b)[0]), "r"((b)[1]))

__device__ __forceinline__ u32 swoff(int r, int kb) {
    u32 off = ((u32)(r >> 3) << 10) + ((u32)(r & 7) << 7) + (u32)kb;
    return off ^ ((off >> 3) & 0x70);
}
__device__ __forceinline__ void atomicMaxF(float* a, float v) {
    atomicMax((int*)a, __float_as_int(v));   // valid: values >= 0
}

// ---------------- transpose in: x (N,C,T) -> g_xt (N,T,C) -------------------
__global__ void k_transpose_in(const float* __restrict__ x) {
    __shared__ float tile[32][33];
    int n = blockIdx.z, t0 = blockIdx.x * 32, c0 = blockIdx.y * 32;
    const float* xin = x + (size_t)n * Cc * Tt;
#pragma unroll
    for (int k = 0; k < 4; k++)
        tile[threadIdx.y + k * 8][threadIdx.x] =
            xin[(size_t)(c0 + threadIdx.y + k * 8) * Tt + t0 + threadIdx.x];
    __syncthreads();
    float* xo = g_xt + (size_t)n * Tt * Cc;
#pragma unroll
    for (int k = 0; k < 4; k++) {
        int t = t0 + threadIdx.y + k * 8;
        xo[(size_t)t * Cc + c0 + threadIdx.x] = tile[threadIdx.x][threadIdx.y + k * 8];
    }
}

__global__ void k_transpose_out(float* __restrict__ out) {
    __shared__ float tile[32][33];
    int n = blockIdx.z, c0 = blockIdx.x * 32, t0 = blockIdx.y * 32;
    const float* fi = g_fhat + (size_t)n * Tt * Cc;
#pragma unroll
    for (int k = 0; k < 4; k++)
        tile[threadIdx.y + k * 8][threadIdx.x] =
            fi[(size_t)(t0 + threadIdx.y + k * 8) * Cc + c0 + threadIdx.x];
    __syncthreads();
    float* oo = out + (size_t)n * Cc * Tt;
#pragma unroll
    for (int k = 0; k < 4; k++)
        oo[(size_t)(c0 + threadIdx.y + k * 8) * Tt + t0 + threadIdx.x] =
            tile[threadIdx.x][threadIdx.y + k * 8];
}

// ------- codebook: half norms + bound constants ----------------------------
__global__ void k_cbhalf(const float* __restrict__ cb) {
    int k = blockIdx.x;
    const float* row = cb + (size_t)k * Cc;
    float s = 0.f, h2 = 0.f, e2 = 0.f;
    for (int i = threadIdx.x; i < Cc; i += 128) {
        float v = row[i];
        float hf = __bfloat162float(__float2bfloat16(v));
        float d = v - hf;
        s += v * v; h2 += hf * hf; e2 += d * d;
    }
#pragma unroll
    for (int o = 16; o; o >>= 1) {
        s  += __shfl_down_sync(0xffffffffu, s,  o);
        h2 += __shfl_down_sync(0xffffffffu, h2, o);
        e2 += __shfl_down_sync(0xffffffffu, e2, o);
    }
    __shared__ float ws[4], wh[4], we[4];
    if ((threadIdx.x & 31) == 0) {
        ws[threadIdx.x >> 5] = s; wh[threadIdx.x >> 5] = h2; we[threadIdx.x >> 5] = e2;
    }
    __syncthreads();
    if (threadIdx.x == 0) {
        float S = ws[0] + ws[1] + ws[2] + ws[3];
        float H = wh[0] + wh[1] + wh[2] + wh[3];
        float E = we[0] + we[1] + we[2] + we[3];
        g_cbhalf[k] = 0.5f * S;
        atomicMaxF(&g_Hy, sqrtf(H));
        atomicMaxF(&g_Ey, sqrtf(E));
    }
}

// ---------------- codebook h-split panels (64 blocks) ------------------------
__global__ void k_cb_split(const float* __restrict__ cb) {
    int panel = blockIdx.x >> 3;
    int seg = blockIdx.x & 7;            // 16 rows per segment
    for (int it = 0; it < 4; it++) {
        int item = seg * 1024 + it * 256 + threadIdx.x;
        int r = item >> 6, kg = item & 63;
        const float4* s4 = (const float4*)(cb + ((size_t)(panel * 128 + r)) * Cc + kg * 8);
        float4 a = s4[0], b = s4[1];
        float f[8] = {a.x, a.y, a.z, a.w, b.x, b.y, b.z, b.w};
        union { __nv_bfloat16 bb[8]; uint4 v; } H;
#pragma unroll
        for (int j = 0; j < 8; j++) H.bb[j] = __float2bfloat16(f[j]);
        u32 sw = swoff(r, (kg & 7) << 4);
        char* pb = (char*)g_cbS + (size_t)panel * PANEL_BYTES
                 + (size_t)(kg >> 3) * CHUNK_BYTES + sw;
        *(uint4*)pb = H.v;
    }
}

// ---------------- scalar prep ----------------------------------------------
__global__ void k_prep_scalars(const int* __restrict__ m_lens) {
    __shared__ int sm[Nn];
    if (threadIdx.x < Nn) sm[threadIdx.x] = m_lens[threadIdx.x];
    __syncthreads();
    if (threadIdx.x == 0) {
        int s = 0;
        for (int i = 0; i < Nn; i++) s += sm[i];
        g_masksum = (float)s;
        g_Hy = 0.f; g_Ey = 0.f;
    }
    if (threadIdx.x < 3) g_err[threadIdx.x] = 0.0;
}
__global__ void k_reset_hist() { g_hist[blockIdx.x * 256 + threadIdx.x] = 0.f; }

// ------- upsample helper: subtract up(j) for 8 channels ----------------------
__device__ __forceinline__ void sub_up8(float* acc, const float* __restrict__ cb,
                                        const int* __restrict__ idxn,
                                        int j, int s_up, int t_up, int tlim, int kgc) {
    float pos = (j + 0.5f) / (float)s_up - 0.5f;
    pos = fminf(fmaxf(pos, 0.0f), (float)(t_up - 1));
    int lo = (int)floorf(pos);
    int hi = min(lo + 1, t_up - 1);
    float w = pos - (float)lo;
    int ilo = (lo < tlim) ? idxn[lo] : -1;
    int ihi = (hi < tlim) ? idxn[hi] : -1;
    float wl = 1.0f - w, wh = w;
    if (ilo >= 0) {
        const float4* p = (const float4*)(cb + (size_t)ilo * Cc + kgc);
        float4 a = p[0], b = p[1];
        acc[0] -= wl * a.x; acc[1] -= wl * a.y; acc[2] -= wl * a.z; acc[3] -= wl * a.w;
        acc[4] -= wl * b.x; acc[5] -= wl * b.y; acc[6] -= wl * b.z; acc[7] -= wl * b.w;
    }
    if (ihi >= 0) {
        const float4* p = (const float4*)(cb + (size_t)ihi * Cc + kgc);
        float4 a = p[0], b = p[1];
        acc[0] -= wh * a.x; acc[1] -= wh * a.y; acc[2] -= wh * a.z; acc[3] -= wh * a.w;
        acc[4] -= wh * b.x; acc[5] -= wh * b.y; acc[6] -= wh * b.z; acc[7] -= wh * b.w;
    }
}

// ------- pooled residual: rd = pool_s(mask * (x - up4 - up2)) ----------------
__global__ void k_pool(const float* __restrict__ cb, const int* __restrict__ m_lens,
                       int s, int t, int stage,
                       const int* __restrict__ idx4, const int* __restrict__ idx2) {
    __shared__ float s_h2[128], s_e2[128];
    int tid = threadIdx.x, panel = blockIdx.x;
    if (tid < 128) { s_h2[tid] = 0.f; s_e2[tid] = 0.f; }
    __syncthreads();
    float inv = 1.0f / (float)s;
    for (int it = 0; it < 32; it++) {
        int item = it * 256 + tid;
        int r = item >> 6, kg = item & 63;
        int kgc = kg * 8;
        int grow = panel * 128 + r;
        int n = grow / t, tp = grow % t;
        int ml = m_lens[n];
        const int* idx4n = idx4 + n * 128;
        const int* idx2n = idx2 + n * 256;
        int tlim4 = ml >> 2, tlim2 = ml >> 1;
        float f[8] = {0.f, 0.f, 0.f, 0.f, 0.f, 0.f, 0.f, 0.f};
        for (int u = 0; u < s; u++) {
            int j = tp * s + u;
            if (j < ml) {
                const float4* s4 =
                    (const float4*)(g_xt + ((size_t)n * Tt + j) * Cc + kgc);
                float4 a = s4[0], b = s4[1];
                float acc[8] = {a.x, a.y, a.z, a.w, b.x, b.y, b.z, b.w};
                if (stage >= 1) sub_up8(acc, cb, idx4n, j, 4, 128, tlim4, kgc);
                if (stage >= 2) sub_up8(acc, cb, idx2n, j, 2, 256, tlim2, kgc);
#pragma unroll
                for (int q = 0; q < 8; q++) f[q] += acc[q];
            }
        }
#pragma unroll
        for (int q = 0; q < 8; q++) f[q] *= inv;
        float4* rp = (float4*)(g_rd + (size_t)grow * Cc + kgc);
        rp[0] = make_float4(f[0], f[1], f[2], f[3]);
        rp[1] = make_float4(f[4], f[5], f[6], f[7]);
        union { __nv_bfloat16 bb[8]; uint4 v; } H;
        float h2 = 0.f, e2 = 0.f;
#pragma unroll
        for (int q = 0; q < 8; q++) {
            __nv_bfloat16 h = __float2bfloat16(f[q]);
            float hf = __bfloat162float(h);
            float d = f[q] - hf;
            H.bb[q] = h; h2 += hf * hf; e2 += d * d;
        }
        u32 sw = swoff(r, (kg & 7) << 4);
        char* pb = (char*)g_rdS + (size_t)panel * PANEL_BYTES
                 + (size_t)(kg >> 3) * CHUNK_BYTES + sw;
        *(uint4*)pb = H.v;
#pragma unroll
        for (int o = 16; o; o >>= 1) {
            h2 += __shfl_down_sync(0xffffffffu, h2, o);
            e2 += __shfl_down_sync(0xffffffffu, e2, o);
        }
        if ((tid & 31) == 0) {
            atomicAdd(&s_h2[r], h2);
            atomicAdd(&s_e2[r], e2);
        }
    }
    __syncthreads();
    if (tid < 128) {
        g_hn[panel * 128 + tid] = sqrtf(s_h2[tid]);
        g_ex[panel * 128 + tid] = sqrtf(s_e2[tid]);
    }
}

// ---------------- pass 1: h.h GEMM -> bf16 scores ----------------------------
__device__ __forceinline__ void fill_stage(u32 stage, const char* A,
                                           const char* B, int tid) {
#pragma unroll
    for (int q = 0; q < 4; q++) {
        int off = (tid + q * 256) * 16;
        cpa16s(stage + off, A + off);
    }
#pragma unroll
    for (int q = 0; q < 4; q++) {
        int off = (tid + q * 256) * 16;
        cpa16s(stage + CHUNK_BYTES + off, B + off);
    }
    CP_COMMIT();
}

__global__ void __launch_bounds__(256, 2)
k_quantize6(const int* __restrict__ m_lens, int t, int scale,
            __nv_bfloat16* __restrict__ score) {
    extern __shared__ char dsm[];
    __shared__ float s_cbh[128];

    int tid = threadIdx.x, wid = tid >> 5, lane = tid & 31;
    int mbase = blockIdx.y * 128;
    int n = mbase / t;
    int tlim = m_lens[n] / scale;
    if (mbase % t >= tlim) return;           // fully masked panel

    u32 dbase = (smem_u32(dsm) + 1023) & ~1023u;
    u32 st0 = dbase, st1 = dbase + 2 * CHUNK_BYTES;

    if (tid < 128) s_cbh[tid] = g_cbhalf[blockIdx.x * 128 + tid];

    const char* A = (const char*)g_rdS + (size_t)blockIdx.y * PANEL_BYTES;
    const char* B = (const char*)g_cbS + (size_t)blockIdx.x * PANEL_BYTES;

    fill_stage(st0, A, B, tid);
    fill_stage(st1, A + CHUNK_BYTES, B + CHUNK_BYTES, tid);

    int warp_m = wid >> 2, warp_n = wid & 3;
    int sub = lane >> 3;
    int a_row = warp_m * 64 + (lane & 7) + ((sub & 1) << 3);
    int a_kb  = (sub >> 1) << 4;
    int b_row = warp_n * 32 + (lane & 7) + ((lane >> 4) << 3);
    int b_kb  = ((lane >> 3) & 1) << 4;

    float acc[4][4][4];
#pragma unroll
    for (int i = 0; i < 4; i++)
#pragma unroll
        for (int j = 0; j < 4; j++)
#pragma unroll
            for (int q = 0; q < 4; q++) acc[i][j][q] = 0.f;

    for (int i = 0; i < GCHUNK; i++) {
        if (i < GCHUNK - 1) CP_WAIT(1); else CP_WAIT(0);
        __syncthreads();
        u32 sa = (i & 1) ? st1 : st0;
        u32 sb = sa + CHUNK_BYTES;
#pragma unroll
        for (int ks = 0; ks < 4; ks++) {
            u32 af[4][4];
#pragma unroll
            for (int mt = 0; mt < 4; mt++) {
                u32 addr = sa + swoff(a_row + mt * 16, ks * 32 + a_kb);
                LDSM4(af[mt][0], af[mt][1], af[mt][2], af[mt][3], addr);
            }
            u32 bf[4][2];
#pragma unroll
            for (int pr = 0; pr < 2; pr++) {
                u32 addr = sb + swoff(b_row + pr * 16, ks * 32 + b_kb);
                LDSM4(bf[2 * pr][0], bf[2 * pr][1],
                      bf[2 * pr + 1][0], bf[2 * pr + 1][1], addr);
            }
#pragma unroll
            for (int mt = 0; mt < 4; mt++)
#pragma unroll
                for (int nt = 0; nt < 4; nt++)
                    MMA16816(acc[mt][nt], af[mt], bf[nt]);
        }
        __syncthreads();
        if (i + 2 < GCHUNK)
            fill_stage((i & 1) ? st1 : st0,
                       A + (size_t)(i + 2) * CHUNK_BYTES,
                       B + (size_t)(i + 2) * CHUNK_BYTES, tid);
    }

    int r0 = warp_m * 64 + (lane >> 2);
    int cbase = warp_n * 32 + (lane & 3) * 2;
#pragma unroll
    for (int mt = 0; mt < 4; mt++) {
#pragma unroll
        for (int nt = 0; nt < 4; nt++) {
            int cl = cbase + nt * 8;
            float h0 = s_cbh[cl], h1 = s_cbh[cl + 1];
            size_t coff = (size_t)blockIdx.x * 128 + cl;
            int grow0 = mbase + r0 + mt * 16;
            *(__nv_bfloat162*)(score + (size_t)grow0 * Kk + coff) =
                __floats2bfloat162_rn(acc[mt][nt][0] - h0, acc[mt][nt][1] - h1);
            *(__nv_bfloat162*)(score + (size_t)(grow0 + 8) * Kk + coff) =
                __floats2bfloat162_rn(acc[mt][nt][2] - h0, acc[mt][nt][3] - h1);
        }
    }
}

// ---------------- rescore: prune + exact fp32 argmax + hist ------------------
__global__ void k_rescore(const float* __restrict__ cb,
                          const int* __restrict__ m_lens,
                          int t, int scale, int* __restrict__ idx_out) {
    int wid = threadIdx.x >> 5, lane = threadIdx.x & 31;
    int row = blockIdx.x * 8 + wid;
    int n = row / t, tr = row % t;
    int tlim = m_lens[n] / scale;
    if (tr >= tlim) {
        if (lane == 0) idx_out[row] = 0;
        return;
    }

    float xr[16];
    const float* xrp = g_rd + (size_t)row * Cc;
#pragma unroll
    for (int c = 0; c < 16; c++) xr[c] = xrp[c * 32 + lane];

    u32 sc[16];
    const u32* su = (const u32*)(g_scoreb + (size_t)row * Kk);
#pragma unroll
    for (int j = 0; j < 16; j++) sc[j] = su[j * 32 + lane];

    float mx = -1e30f;
#pragma unroll
    for (int j = 0; j < 16; j++) {
        float s0 = __uint_as_float(sc[j] << 16);
        float s1 = __uint_as_float(sc[j] & 0xffff0000u);
        mx = fmaxf(mx, fmaxf(s0, s1));
    }
#pragma unroll
    for (int o = 16; o; o >>= 1) mx = fmaxf(mx, __shfl_xor_sync(0xffffffffu, mx, o));

    float B = 1.02f * (g_hn[row] * g_Ey + g_ex[row] * (g_Hy + g_Ey)) + 1e-2f;
    float eps = 0.004f * (fabsf(mx) + 2.0f * B) + 1e-2f;   // bf16 rounding margin
    float tau = mx - 2.0f * B - 2.0f * eps;

    float best = -1e30f; int bi = 0;
    for (int j = 0; j < 16; j++) {
        float s0 = __uint_as_float(sc[j] << 16);
        float s1 = __uint_as_float(sc[j] & 0xffff0000u);
        unsigned m = __ballot_sync(0xffffffffu, (s0 >= tau) || (s1 >= tau));
        while (m) {
            int l = __ffs(m) - 1; m &= m - 1;
            u32 uv = __shfl_sync(0xffffffffu, sc[j], l);
            float t0 = __uint_as_float(uv << 16);
            float t1 = __uint_as_float(uv & 0xffff0000u);
            int k0 = (j * 32 + l) * 2;
#pragma unroll
            for (int h = 0; h < 2; h++) {
                float sv_b = h ? t1 : t0;
                if (sv_b < tau) continue;
                int k = k0 + h;
                const float* cbk = cb + (size_t)k * Cc;
                float p = 0.f;
#pragma unroll
                for (int c = 0; c < 16; c++) p = fmaf(xr[c], cbk[c * 32 + lane], p);
#pragma unroll
                for (int o = 16; o; o >>= 1) p += __shfl_xor_sync(0xffffffffu, p, o);
                float sv = p - g_cbhalf[k];
                if (sv > best) { best = sv; bi = k; }   // ascending k: first max wins
            }
        }
    }
    if (lane == 0) {
        idx_out[row] = bi;
        atomicAdd(&g_hist[bi], 1.0f);
    }
}

// ------- final: f_hat = up4+up2+up1, all three loss terms, one pass ----------
__global__ void k_final(const float* __restrict__ cb,
                        const int* __restrict__ m_lens,
                        const int* __restrict__ idx4,
                        const int* __restrict__ idx2,
                        const int* __restrict__ idx1) {
    int g = blockIdx.x;
    int n = g / Tt, j = g % Tt;
    int ml = m_lens[n];
    int i = threadIdx.x;               // 128 threads == C/4
    size_t base = ((size_t)n * Tt + j) * (Cc / 4);

    float4 u[3];
    const int* idxs[3] = {idx4 + n * 128, idx2 + n * 256, idx1 + n * 512};
    const int sups[3] = {4, 2, 1};
    const int tups[3] = {128, 256, 512};
#pragma unroll
    for (int q = 0; q < 3; q++) {
        int s_up = sups[q], t_up = tups[q];
        int tlim = ml / s_up;
        float pos = (j + 0.5f) / (float)s_up - 0.5f;
        pos = fminf(fmaxf(pos, 0.0f), (float)(t_up - 1));
        int lo = (int)floorf(pos);
        int hi = min(lo + 1, t_up - 1);
        float w = pos - (float)lo;
        int ilo = (lo < tlim) ? idxs[q][lo] : -1;
        int ihi = (hi < tlim) ? idxs[q][hi] : -1;
        float wl = 1.0f - w, wh = w;
        float4 up = make_float4(0.f, 0.f, 0.f, 0.f);
        if (ilo >= 0) {
            float4 v = ((const float4*)(cb + (size_t)ilo * Cc))[i];
            up.x += wl * v.x; up.y += wl * v.y; up.z += wl * v.z; up.w += wl * v.w;
        }
        if (ihi >= 0) {
            float4 v = ((const float4*)(cb + (size_t)ihi * Cc))[i];
            up.x += wh * v.x; up.y += wh * v.y; up.z += wh * v.z; up.w += wh * v.w;
        }
        u[q] = up;
    }
    float4 f1 = u[0];
    float4 f2 = make_float4(f1.x + u[1].x, f1.y + u[1].y, f1.z + u[1].z, f1.w + u[1].w);
    float4 f3 = make_float4(f2.x + u[2].x, f2.y + u[2].y, f2.z + u[2].z, f2.w + u[2].w);
    ((float4*)g_fhat)[base + i] = f3;

    float lsum = 0.f;
    if (j < ml) {
        float4 xv = ((const float4*)g_xt)[base + i];
        float e;
        e = xv.x - f1.x; lsum += e * e;  e = xv.y - f1.y; lsum += e * e;
        e = xv.z - f1.z; lsum += e * e;  e = xv.w - f1.w; lsum += e * e;
        e = xv.x - f2.x; lsum += e * e;  e = xv.y - f2.y; lsum += e * e;
        e = xv.z - f2.z; lsum += e * e;  e = xv.w - f2.w; lsum += e * e;
        e = xv.x - f3.x; lsum += e * e;  e = xv.y - f3.y; lsum += e * e;
        e = xv.z - f3.z; lsum += e * e;  e = xv.w - f3.w; lsum += e * e;
    }
#pragma unroll
    for (int o = 16; o; o >>= 1) lsum += __shfl_down_sync(0xffffffffu, lsum, o);
    __shared__ float ws[4];
    if ((threadIdx.x & 31) == 0) ws[threadIdx.x >> 5] = lsum;
    __syncthreads();
    if (threadIdx.x == 0 && j < ml)
        atomicAdd(&g_err[0], (double)(ws[0] + ws[1] + ws[2] + ws[3]));
}

// ---------------- finalize ---------------------------------------------------
__global__ void k_finalize(float* __restrict__ out) {
    int tid = threadIdx.x;
    float c = g_hist[tid];
    __shared__ float ws[32];
    float v = c;
#pragma unroll
    for (int o = 16; o; o >>= 1) v += __shfl_down_sync(0xffffffffu, v, o);
    if ((tid & 31) == 0) ws[tid >> 5] = v;
    __syncthreads();
    if (tid < 32) {
        float z = ws[tid];
#pragma unroll
        for (int o = 16; o; o >>= 1) z += __shfl_down_sync(0xffffffffu, z, o);
        if (tid == 0) ws[0] = z;
    }
    __syncthreads();
    float total = ws[0];
    __syncthreads();
    float p = c / total;
    float e = p * logf(p + 1e-7f);
#pragma unroll
    for (int o = 16; o; o >>= 1) e += __shfl_down_sync(0xffffffffu, e, o);
    if ((tid & 31) == 0) ws[tid >> 5] = e;
    __syncthreads();
    if (tid == 0) {
        float ent = 0.f;
        for (int i = 0; i < 32; i++) ent += ws[i];
        double denom = (double)g_masksum * (double)Tt;
        double loss = (g_err[0] + g_err[1] + g_err[2]) / denom / 3.0;
        out[NCT]     = (float)loss;
        out[NCT + 1] = expf(-ent);
    }
}

// ---------------- launch ------------------------------------------------------
extern "C" void kernel_launch(void* const* d_in, const int* in_sizes, int n_in,
                              void* d_out, int out_size) {
    const float* x = nullptr; const float* cb = nullptr; const int* m_lens = nullptr;
    for (int i = 0; i < n_in; i++) {
        if (in_sizes[i] == NCT)            x = (const float*)d_in[i];
        else if (in_sizes[i] == Kk * Cc)   cb = (const float*)d_in[i];
        else if (in_sizes[i] == Nn)        m_lens = (const int*)d_in[i];
    }
    float* out = (float*)d_out;

    const int DYN = 1024 + 4 * CHUNK_BYTES;
    cudaFuncSetAttribute(k_quantize6, cudaFuncAttributeMaxDynamicSharedMemorySize, DYN);

    void* idxv = nullptr; cudaGetSymbolAddress(&idxv, g_idx);
    int* idxbase = (int*)idxv;
    void* scv = nullptr;  cudaGetSymbolAddress(&scv, g_scoreb);
    __nv_bfloat16* score = (__nv_bfloat16*)scv;

    int* idx4 = idxbase;
    int* idx2 = idxbase + Nn * 128;
    int* idx1 = idxbase + Nn * 128 + Nn * 256;
    int* idxs[3] = {idx4, idx2, idx1};

    k_reset_hist<<<4, 256>>>();
    k_prep_scalars<<<1, 64>>>(m_lens);
    k_cbhalf<<<Kk, 128>>>(cb);
    k_cb_split<<<64, 256>>>(cb);
    {
        dim3 gb(Tt / 32, Cc / 32, Nn), tb(32, 8);
        k_transpose_in<<<gb, tb>>>(x);
    }

    const int scales[3] = {4, 2, 1};
    for (int s = 0; s < 3; s++) {
        int sc = scales[s], t = Tt / sc, M = Nn * t;
        int panels = M / 128;
        k_pool<<<panels, 256>>>(cb, m_lens, sc, t, s, idx4, idx2);
        k_quantize6<<<dim3(8, panels), 256, DYN>>>(m_lens, t, sc, score);
        k_rescore<<<M / 8, 256>>>(cb, m_lens, t, sc, idxs[s]);
    }

    k_final<<<Nn * Tt, 128>>>(cb, m_lens, idx4, idx2, idx1);
    k_finalize<<<1, 1024>>>(out);
    {
        dim3 gb(Cc / 32, Tt / 32, Nn), tb(32, 8);
        k_transpose_out<<<gb, tb>>>(out);
    }
}

// round 11
// speedup vs baseline: 1.1152x; 1.0201x over previous
#include <cuda_runtime.h>
#include <cuda_bf16.h>
#include <math.h>

#define Nn 64
#define Cc 512
#define Tt 512
#define Kk 1024
#define NCT (Nn*Cc*Tt)

#define GCHUNK 8                // K' = 512 bf16 (h.h only) = 8 chunks of 64
#define CHUNK_BYTES 16384       // 128 rows x 64 bf16 (SW128-swizzled)
#define PANEL_BYTES (GCHUNK*CHUNK_BYTES)   // 128 KB
#define PANEL_ELEMS (GCHUNK*8192)

typedef unsigned int u32;
typedef unsigned long long u64;

// ---------------- device scratch ------------------------------------------
__device__ float  g_xt[NCT];                             // x in (N,T,C)
__device__ float  g_rd[32768 * Cc];                      // pooled rows fp32
__device__ __nv_bfloat16 g_scoreb[32768 * Kk];           // pass-1 scores (bf16)
__device__ __align__(16) __nv_bfloat16 g_rdS[256 * PANEL_ELEMS]; // h split A
__device__ __align__(16) __nv_bfloat16 g_cbS[8   * PANEL_ELEMS]; // h split B
__device__ int    g_idx[Nn*(128+256+512)];
__device__ float  g_cbhalf[Kk];
__device__ float  g_hn[32768];   // ||h_x|| per row
__device__ float  g_ex[32768];   // ||x - h_x|| per row
__device__ float  g_Hy, g_Ey;    // max ||h_k||, max ||cb_k - h_k||
__device__ float  g_hist[Kk];
__device__ double g_err[3];
__device__ float  g_masksum;

// ---------------- PTX helpers ---------------------------------------------
__device__ __forceinline__ u32 smem_u32(const void* p) {
    u32 a;
    asm("{ .reg .u64 t; cvta.to.shared.u64 t, %1; cvt.u32.u64 %0, t; }" : "=r"(a) : "l"(p));
    return a;
}
__device__ __forceinline__ void cpa16s(u32 dst, const void* src) {
    asm volatile("cp.async.cg.shared.global [%0], [%1], 16;" :: "r"(dst), "l"(src));
}
#define CP_COMMIT() asm volatile("cp.async.commit_group;" ::: "memory")
#define CP_WAIT(n)  asm volatile("cp.async.wait_group %0;" :: "n"(n) : "memory")

#define LDSM4(r0, r1, r2, r3, a) \
    asm volatile("ldmatrix.sync.aligned.m8n8.x4.shared.b16 {%0,%1,%2,%3}, [%4];" \
                 : "=r"(r0), "=r"(r1), "=r"(r2), "=r"(r3) : "r"(a))

#define MMA16816(c, a, b) \
    asm volatile("mma.sync.aligned.m16n8k16.row.col.f32.bf16.bf16.f32 " \
                 "{%0,%1,%2,%3}, {%4,%5,%6,%7}, {%8,%9}, {%0,%1,%2,%3};" \
                 : "+f"((c)[0]), "+f"((c)[1]), "+f"((c)[2]), "+f"((c)[3]) \
                 : "r"((a)[0]), "r"((a)[1]), "r"((a)[2]), "r"((a)[3]), \
                   "r"((b)[0]), "r"((b)[1]))

__device__ __forceinline__ u32 swoff(int r, int kb) {
    u32 off = ((u32)(r >> 3) << 10) + ((u32)(r & 7) << 7) + (u32)kb;
    return off ^ ((off >> 3) & 0x70);
}
__device__ __forceinline__ void atomicMaxF(float* a, float v) {
    atomicMax((int*)a, __float_as_int(v));   // valid: values >= 0
}

// ---------------- transpose in: x (N,C,T) -> g_xt (N,T,C) -------------------
__global__ void k_transpose_in(const float* __restrict__ x) {
    __shared__ float tile[32][33];
    int n = blockIdx.z, t0 = blockIdx.x * 32, c0 = blockIdx.y * 32;
    const float* xin = x + (size_t)n * Cc * Tt;
#pragma unroll
    for (int k = 0; k < 4; k++)
        tile[threadIdx.y + k * 8][threadIdx.x] =
            xin[(size_t)(c0 + threadIdx.y + k * 8) * Tt + t0 + threadIdx.x];
    __syncthreads();
    float* xo = g_xt + (size_t)n * Tt * Cc;
#pragma unroll
    for (int k = 0; k < 4; k++) {
        int t = t0 + threadIdx.y + k * 8;
        xo[(size_t)t * Cc + c0 + threadIdx.x] = tile[threadIdx.x][threadIdx.y + k * 8];
    }
}

// ------- codebook: half norms + bound constants ----------------------------
__global__ void k_cbhalf(const float* __restrict__ cb) {
    int k = blockIdx.x;
    const float* row = cb + (size_t)k * Cc;
    float s = 0.f, h2 = 0.f, e2 = 0.f;
    for (int i = threadIdx.x; i < Cc; i += 128) {
        float v = row[i];
        float hf = __bfloat162float(__float2bfloat16(v));
        float d = v - hf;
        s += v * v; h2 += hf * hf; e2 += d * d;
    }
#pragma unroll
    for (int o = 16; o; o >>= 1) {
        s  += __shfl_down_sync(0xffffffffu, s,  o);
        h2 += __shfl_down_sync(0xffffffffu, h2, o);
        e2 += __shfl_down_sync(0xffffffffu, e2, o);
    }
    __shared__ float ws[4], wh[4], we[4];
    if ((threadIdx.x & 31) == 0) {
        ws[threadIdx.x >> 5] = s; wh[threadIdx.x >> 5] = h2; we[threadIdx.x >> 5] = e2;
    }
    __syncthreads();
    if (threadIdx.x == 0) {
        float S = ws[0] + ws[1] + ws[2] + ws[3];
        float H = wh[0] + wh[1] + wh[2] + wh[3];
        float E = we[0] + we[1] + we[2] + we[3];
        g_cbhalf[k] = 0.5f * S;
        atomicMaxF(&g_Hy, sqrtf(H));
        atomicMaxF(&g_Ey, sqrtf(E));
    }
}

// ---------------- codebook h-split panels (64 blocks) ------------------------
__global__ void k_cb_split(const float* __restrict__ cb) {
    int panel = blockIdx.x >> 3;
    int seg = blockIdx.x & 7;            // 16 rows per segment
    for (int it = 0; it < 4; it++) {
        int item = seg * 1024 + it * 256 + threadIdx.x;
        int r = item >> 6, kg = item & 63;
        const float4* s4 = (const float4*)(cb + ((size_t)(panel * 128 + r)) * Cc + kg * 8);
        float4 a = s4[0], b = s4[1];
        float f[8] = {a.x, a.y, a.z, a.w, b.x, b.y, b.z, b.w};
        union { __nv_bfloat16 bb[8]; uint4 v; } H;
#pragma unroll
        for (int j = 0; j < 8; j++) H.bb[j] = __float2bfloat16(f[j]);
        u32 sw = swoff(r, (kg & 7) << 4);
        char* pb = (char*)g_cbS + (size_t)panel * PANEL_BYTES
                 + (size_t)(kg >> 3) * CHUNK_BYTES + sw;
        *(uint4*)pb = H.v;
    }
}

// ---------------- scalar prep (merged: hist reset + scalars) ----------------
__global__ void k_prep(const int* __restrict__ m_lens) {
    int tid = threadIdx.x;                 // 1024 threads
    g_hist[tid] = 0.f;
    __shared__ int sm[Nn];
    if (tid < Nn) sm[tid] = m_lens[tid];
    __syncthreads();
    if (tid == 0) {
        int s = 0;
        for (int i = 0; i < Nn; i++) s += sm[i];
        g_masksum = (float)s;
        g_Hy = 0.f; g_Ey = 0.f;
    }
    if (tid < 3) g_err[tid] = 0.0;
}

// ------- upsample helper: subtract up(j) for 8 channels ----------------------
__device__ __forceinline__ void sub_up8(float* acc, const float* __restrict__ cb,
                                        const int* __restrict__ idxn,
                                        int j, int s_up, int t_up, int tlim, int kgc) {
    float pos = (j + 0.5f) / (float)s_up - 0.5f;
    pos = fminf(fmaxf(pos, 0.0f), (float)(t_up - 1));
    int lo = (int)floorf(pos);
    int hi = min(lo + 1, t_up - 1);
    float w = pos - (float)lo;
    int ilo = (lo < tlim) ? idxn[lo] : -1;
    int ihi = (hi < tlim) ? idxn[hi] : -1;
    float wl = 1.0f - w, wh = w;
    if (ilo >= 0) {
        const float4* p = (const float4*)(cb + (size_t)ilo * Cc + kgc);
        float4 a = p[0], b = p[1];
        acc[0] -= wl * a.x; acc[1] -= wl * a.y; acc[2] -= wl * a.z; acc[3] -= wl * a.w;
        acc[4] -= wl * b.x; acc[5] -= wl * b.y; acc[6] -= wl * b.z; acc[7] -= wl * b.w;
    }
    if (ihi >= 0) {
        const float4* p = (const float4*)(cb + (size_t)ihi * Cc + kgc);
        float4 a = p[0], b = p[1];
        acc[0] -= wh * a.x; acc[1] -= wh * a.y; acc[2] -= wh * a.z; acc[3] -= wh * a.w;
        acc[4] -= wh * b.x; acc[5] -= wh * b.y; acc[6] -= wh * b.z; acc[7] -= wh * b.w;
    }
}

// ------- pooled residual: rd = pool_s(mask * (x - up4 - up2)) ----------------
__global__ void k_pool(const float* __restrict__ cb, const int* __restrict__ m_lens,
                       int s, int t, int stage,
                       const int* __restrict__ idx4, const int* __restrict__ idx2) {
    __shared__ float s_h2[128], s_e2[128];
    int tid = threadIdx.x, panel = blockIdx.x;
    if (tid < 128) { s_h2[tid] = 0.f; s_e2[tid] = 0.f; }
    __syncthreads();
    float inv = 1.0f / (float)s;
    for (int it = 0; it < 32; it++) {
        int item = it * 256 + tid;
        int r = item >> 6, kg = item & 63;
        int kgc = kg * 8;
        int grow = panel * 128 + r;
        int n = grow / t, tp = grow % t;
        int ml = m_lens[n];
        int tlimS = ml / s;
        if (tp >= tlimS) continue;          // dead row: no writes needed
        const int* idx4n = idx4 + n * 128;
        const int* idx2n = idx2 + n * 256;
        int tlim4 = ml >> 2, tlim2 = ml >> 1;
        float f[8] = {0.f, 0.f, 0.f, 0.f, 0.f, 0.f, 0.f, 0.f};
        for (int u = 0; u < s; u++) {
            int j = tp * s + u;
            if (j < ml) {
                const float4* s4 =
                    (const float4*)(g_xt + ((size_t)n * Tt + j) * Cc + kgc);
                float4 a = s4[0], b = s4[1];
                float acc[8] = {a.x, a.y, a.z, a.w, b.x, b.y, b.z, b.w};
                if (stage >= 1) sub_up8(acc, cb, idx4n, j, 4, 128, tlim4, kgc);
                if (stage >= 2) sub_up8(acc, cb, idx2n, j, 2, 256, tlim2, kgc);
#pragma unroll
                for (int q = 0; q < 8; q++) f[q] += acc[q];
            }
        }
#pragma unroll
        for (int q = 0; q < 8; q++) f[q] *= inv;
        float4* rp = (float4*)(g_rd + (size_t)grow * Cc + kgc);
        rp[0] = make_float4(f[0], f[1], f[2], f[3]);
        rp[1] = make_float4(f[4], f[5], f[6], f[7]);
        union { __nv_bfloat16 bb[8]; uint4 v; } H;
        float h2 = 0.f, e2 = 0.f;
#pragma unroll
        for (int q = 0; q < 8; q++) {
            __nv_bfloat16 h = __float2bfloat16(f[q]);
            float hf = __bfloat162float(h);
            float d = f[q] - hf;
            H.bb[q] = h; h2 += hf * hf; e2 += d * d;
        }
        u32 sw = swoff(r, (kg & 7) << 4);
        char* pb = (char*)g_rdS + (size_t)panel * PANEL_BYTES
                 + (size_t)(kg >> 3) * CHUNK_BYTES + sw;
        *(uint4*)pb = H.v;
#pragma unroll
        for (int o = 16; o; o >>= 1) {
            h2 += __shfl_down_sync(0xffffffffu, h2, o);
            e2 += __shfl_down_sync(0xffffffffu, e2, o);
        }
        if ((tid & 31) == 0) {
            atomicAdd(&s_h2[r], h2);
            atomicAdd(&s_e2[r], e2);
        }
    }
    __syncthreads();
    if (tid < 128) {
        g_hn[panel * 128 + tid] = sqrtf(s_h2[tid]);
        g_ex[panel * 128 + tid] = sqrtf(s_e2[tid]);
    }
}

// ---------------- pass 1: h.h GEMM -> bf16 scores ----------------------------
__device__ __forceinline__ void fill_stage(u32 stage, const char* A,
                                           const char* B, int tid) {
#pragma unroll
    for (int q = 0; q < 4; q++) {
        int off = (tid + q * 256) * 16;
        cpa16s(stage + off, A + off);
    }
#pragma unroll
    for (int q = 0; q < 4; q++) {
        int off = (tid + q * 256) * 16;
        cpa16s(stage + CHUNK_BYTES + off, B + off);
    }
    CP_COMMIT();
}

__global__ void __launch_bounds__(256, 2)
k_quantize6(const int* __restrict__ m_lens, int t, int scale,
            __nv_bfloat16* __restrict__ score) {
    extern __shared__ char dsm[];
    __shared__ float s_cbh[128];

    int tid = threadIdx.x, wid = tid >> 5, lane = tid & 31;
    int mbase = blockIdx.y * 128;
    int n = mbase / t;
    int tlim = m_lens[n] / scale;
    if (mbase % t >= tlim) return;           // fully masked panel

    u32 dbase = (smem_u32(dsm) + 1023) & ~1023u;
    u32 st0 = dbase, st1 = dbase + 2 * CHUNK_BYTES;

    if (tid < 128) s_cbh[tid] = g_cbhalf[blockIdx.x * 128 + tid];

    const char* A = (const char*)g_rdS + (size_t)blockIdx.y * PANEL_BYTES;
    const char* B = (const char*)g_cbS + (size_t)blockIdx.x * PANEL_BYTES;

    fill_stage(st0, A, B, tid);
    fill_stage(st1, A + CHUNK_BYTES, B + CHUNK_BYTES, tid);

    int warp_m = wid >> 2, warp_n = wid & 3;
    int sub = lane >> 3;
    int a_row = warp_m * 64 + (lane & 7) + ((sub & 1) << 3);
    int a_kb  = (sub >> 1) << 4;
    int b_row = warp_n * 32 + (lane & 7) + ((lane >> 4) << 3);
    int b_kb  = ((lane >> 3) & 1) << 4;

    float acc[4][4][4];
#pragma unroll
    for (int i = 0; i < 4; i++)
#pragma unroll
        for (int j = 0; j < 4; j++)
#pragma unroll
            for (int q = 0; q < 4; q++) acc[i][j][q] = 0.f;

    for (int i = 0; i < GCHUNK; i++) {
        if (i < GCHUNK - 1) CP_WAIT(1); else CP_WAIT(0);
        __syncthreads();
        u32 sa = (i & 1) ? st1 : st0;
        u32 sb = sa + CHUNK_BYTES;
#pragma unroll
        for (int ks = 0; ks < 4; ks++) {
            u32 af[4][4];
#pragma unroll
            for (int mt = 0; mt < 4; mt++) {
                u32 addr = sa + swoff(a_row + mt * 16, ks * 32 + a_kb);
                LDSM4(af[mt][0], af[mt][1], af[mt][2], af[mt][3], addr);
            }
            u32 bf[4][2];
#pragma unroll
            for (int pr = 0; pr < 2; pr++) {
                u32 addr = sb + swoff(b_row + pr * 16, ks * 32 + b_kb);
                LDSM4(bf[2 * pr][0], bf[2 * pr][1],
                      bf[2 * pr + 1][0], bf[2 * pr + 1][1], addr);
            }
#pragma unroll
            for (int mt = 0; mt < 4; mt++)
#pragma unroll
                for (int nt = 0; nt < 4; nt++)
                    MMA16816(acc[mt][nt], af[mt], bf[nt]);
        }
        __syncthreads();
        if (i + 2 < GCHUNK)
            fill_stage((i & 1) ? st1 : st0,
                       A + (size_t)(i + 2) * CHUNK_BYTES,
                       B + (size_t)(i + 2) * CHUNK_BYTES, tid);
    }

    int r0 = warp_m * 64 + (lane >> 2);
    int cbase = warp_n * 32 + (lane & 3) * 2;
    int trow0 = mbase % t;
#pragma unroll
    for (int mt = 0; mt < 4; mt++) {
        int rr0 = r0 + mt * 16;
        bool live0 = (trow0 + rr0)     < tlim;
        bool live1 = (trow0 + rr0 + 8) < tlim;
#pragma unroll
        for (int nt = 0; nt < 4; nt++) {
            int cl = cbase + nt * 8;
            float h0 = s_cbh[cl], h1 = s_cbh[cl + 1];
            size_t coff = (size_t)blockIdx.x * 128 + cl;
            int grow0 = mbase + rr0;
            if (live0)
                *(__nv_bfloat162*)(score + (size_t)grow0 * Kk + coff) =
                    __floats2bfloat162_rn(acc[mt][nt][0] - h0, acc[mt][nt][1] - h1);
            if (live1)
                *(__nv_bfloat162*)(score + (size_t)(grow0 + 8) * Kk + coff) =
                    __floats2bfloat162_rn(acc[mt][nt][2] - h0, acc[mt][nt][3] - h1);
        }
    }
}

// ---------------- rescore: prune + exact fp32 argmax + hist ------------------
__global__ void k_rescore(const float* __restrict__ cb,
                          const int* __restrict__ m_lens,
                          int t, int scale, int* __restrict__ idx_out) {
    int wid = threadIdx.x >> 5, lane = threadIdx.x & 31;
    int row = blockIdx.x * 8 + wid;
    int n = row / t, tr = row % t;
    int tlim = m_lens[n] / scale;
    if (tr >= tlim) {
        if (lane == 0) idx_out[row] = 0;
        return;
    }

    float xr[16];
    const float* xrp = g_rd + (size_t)row * Cc;
#pragma unroll
    for (int c = 0; c < 16; c++) xr[c] = xrp[c * 32 + lane];

    u32 sc[16];
    const u32* su = (const u32*)(g_scoreb + (size_t)row * Kk);
#pragma unroll
    for (int j = 0; j < 16; j++) sc[j] = su[j * 32 + lane];

    float mx = -1e30f;
#pragma unroll
    for (int j = 0; j < 16; j++) {
        float s0 = __uint_as_float(sc[j] << 16);
        float s1 = __uint_as_float(sc[j] & 0xffff0000u);
        mx = fmaxf(mx, fmaxf(s0, s1));
    }
#pragma unroll
    for (int o = 16; o; o >>= 1) mx = fmaxf(mx, __shfl_xor_sync(0xffffffffu, mx, o));

    float B = 1.02f * (g_hn[row] * g_Ey + g_ex[row] * (g_Hy + g_Ey)) + 1e-2f;
    float eps = 0.004f * (fabsf(mx) + 2.0f * B) + 1e-2f;   // bf16 rounding margin
    float tau = mx - 2.0f * B - 2.0f * eps;

    float best = -1e30f; int bi = 0;
    for (int j = 0; j < 16; j++) {
        float s0 = __uint_as_float(sc[j] << 16);
        float s1 = __uint_as_float(sc[j] & 0xffff0000u);
        unsigned m = __ballot_sync(0xffffffffu, (s0 >= tau) || (s1 >= tau));
        while (m) {
            int l = __ffs(m) - 1; m &= m - 1;
            u32 uv = __shfl_sync(0xffffffffu, sc[j], l);
            float t0 = __uint_as_float(uv << 16);
            float t1 = __uint_as_float(uv & 0xffff0000u);
            int k0 = (j * 32 + l) * 2;
#pragma unroll
            for (int h = 0; h < 2; h++) {
                float sv_b = h ? t1 : t0;
                if (sv_b < tau) continue;
                int k = k0 + h;
                const float* cbk = cb + (size_t)k * Cc;
                float p = 0.f;
#pragma unroll
                for (int c = 0; c < 16; c++) p = fmaf(xr[c], cbk[c * 32 + lane], p);
#pragma unroll
                for (int o = 16; o; o >>= 1) p += __shfl_xor_sync(0xffffffffu, p, o);
                float sv = p - g_cbhalf[k];
                if (sv > best) { best = sv; bi = k; }   // ascending k: first max wins
            }
        }
    }
    if (lane == 0) {
        idx_out[row] = bi;
        atomicAdd(&g_hist[bi], 1.0f);
    }
}

// ------- fused output v2: f_hat + loss + transpose, full-C blocks ------------
// grid (Tt/32, Nn), 256 threads. Tile in DYNAMIC smem (512x33 fp32 = 67.6 KB).
#define OUT2_TILE_FLOATS (Cc * 33)
#define OUT2_DYN (OUT2_TILE_FLOATS * 4)

__global__ void __launch_bounds__(256)
k_out2(const float* __restrict__ cb, const int* __restrict__ m_lens,
       const int* __restrict__ idx4, const int* __restrict__ idx2,
       const int* __restrict__ idx1, float* __restrict__ out) {
    extern __shared__ float tile[];      // [c][t] padded stride 33
    __shared__ int   s_ilo[3][32], s_ihi[3][32];
    __shared__ float s_w[3][32];
    __shared__ float ws[8];

    int tid = threadIdx.x;
    int n = blockIdx.y, t0 = blockIdx.x * 32;
    int ml = m_lens[n];

    // phase A: idx/weights for 32 t x 3 scales (threads 0..95)
    if (tid < 96) {
        int q = tid >> 5, tt = tid & 31;
        const int sups[3] = {4, 2, 1};
        const int tups[3] = {128, 256, 512};
        int s_up = sups[q], t_up = tups[q];
        int tlim = ml / s_up;
        int j = t0 + tt;
        float pos = (j + 0.5f) / (float)s_up - 0.5f;
        pos = fminf(fmaxf(pos, 0.0f), (float)(t_up - 1));
        int lo = (int)floorf(pos);
        int hi = min(lo + 1, t_up - 1);
        float w = pos - (float)lo;
        const int* idxn = (q == 0) ? (idx4 + n * 128)
                        : (q == 1) ? (idx2 + n * 256)
                                   : (idx1 + n * 512);
        s_ilo[q][tt] = (lo < tlim) ? idxn[lo] : -1;
        s_ihi[q][tt] = (hi < tlim) ? idxn[hi] : -1;
        s_w[q][tt] = w;
    }
    __syncthreads();

    // phase B: each thread = one c-quad (cq 0..127) x 16 t's
    int cq = tid & 127;                  // float4 channel group
    int tg = tid >> 7;                   // 0 or 1
    float lacc = 0.f;
    for (int ti = 0; ti < 16; ti++) {
        int tt = tg * 16 + ti;
        int t = t0 + tt;
        float4 f[3];
#pragma unroll
        for (int q = 0; q < 3; q++) {
            int ilo = s_ilo[q][tt], ihi = s_ihi[q][tt];
            float w = s_w[q][tt];
            float wl = 1.0f - w;
            float4 up = make_float4(0.f, 0.f, 0.f, 0.f);
            if (ilo >= 0) {
                float4 v = ((const float4*)(cb + (size_t)ilo * Cc))[cq];
                up.x += wl * v.x; up.y += wl * v.y; up.z += wl * v.z; up.w += wl * v.w;
            }
            if (ihi >= 0) {
                float4 v = ((const float4*)(cb + (size_t)ihi * Cc))[cq];
                up.x += w * v.x; up.y += w * v.y; up.z += w * v.z; up.w += w * v.w;
            }
            f[q] = up;
        }
        float4 f1 = f[0];
        float4 f2 = make_float4(f1.x + f[1].x, f1.y + f[1].y, f1.z + f[1].z, f1.w + f[1].w);
        float4 f3 = make_float4(f2.x + f[2].x, f2.y + f[2].y, f2.z + f[2].z, f2.w + f[2].w);
        int c0 = cq * 4;
        tile[(c0 + 0) * 33 + tt] = f3.x;
        tile[(c0 + 1) * 33 + tt] = f3.y;
        tile[(c0 + 2) * 33 + tt] = f3.z;
        tile[(c0 + 3) * 33 + tt] = f3.w;
        if (t < ml) {
            float4 xv = ((const float4*)(g_xt + ((size_t)n * Tt + t) * Cc))[cq];
            float e;
            e = xv.x - f1.x; lacc += e * e;  e = xv.y - f1.y; lacc += e * e;
            e = xv.z - f1.z; lacc += e * e;  e = xv.w - f1.w; lacc += e * e;
            e = xv.x - f2.x; lacc += e * e;  e = xv.y - f2.y; lacc += e * e;
            e = xv.z - f2.z; lacc += e * e;  e = xv.w - f2.w; lacc += e * e;
            e = xv.x - f3.x; lacc += e * e;  e = xv.y - f3.y; lacc += e * e;
            e = xv.z - f3.z; lacc += e * e;  e = xv.w - f3.w; lacc += e * e;
        }
    }
#pragma unroll
    for (int o = 16; o; o >>= 1) lacc += __shfl_down_sync(0xffffffffu, lacc, o);
    if ((tid & 31) == 0) ws[tid >> 5] = lacc;
    __syncthreads();
    if (tid == 0) {
        float s = 0.f;
        for (int q = 0; q < 8; q++) s += ws[q];
        atomicAdd(&g_err[0], (double)s);
    }

    // phase C: coalesced write out[n][c][t0:t0+32]
    float* oo = out + (size_t)n * Cc * Tt + t0;
    for (int r = tid; r < Cc * 8; r += 256) {     // 512 rows x 8 float4
        int c = r >> 3, fc = (r & 7) * 4;
        float4 v = make_float4(tile[c * 33 + fc],     tile[c * 33 + fc + 1],
                               tile[c * 33 + fc + 2], tile[c * 33 + fc + 3]);
        *(float4*)(oo + (size_t)c * Tt + fc) = v;
    }
}

// ---------------- finalize ---------------------------------------------------
__global__ void k_finalize(float* __restrict__ out) {
    int tid = threadIdx.x;
    float c = g_hist[tid];
    __shared__ float ws[32];
    float v = c;
#pragma unroll
    for (int o = 16; o; o >>= 1) v += __shfl_down_sync(0xffffffffu, v, o);
    if ((tid & 31) == 0) ws[tid >> 5] = v;
    __syncthreads();
    if (tid < 32) {
        float z = ws[tid];
#pragma unroll
        for (int o = 16; o; o >>= 1) z += __shfl_down_sync(0xffffffffu, z, o);
        if (tid == 0) ws[0] = z;
    }
    __syncthreads();
    float total = ws[0];
    __syncthreads();
    float p = c / total;
    float e = p * logf(p + 1e-7f);
#pragma unroll
    for (int o = 16; o; o >>= 1) e += __shfl_down_sync(0xffffffffu, e, o);
    if ((tid & 31) == 0) ws[tid >> 5] = e;
    __syncthreads();
    if (tid == 0) {
        float ent = 0.f;
        for (int i = 0; i < 32; i++) ent += ws[i];
        double denom = (double)g_masksum * (double)Tt;
        double loss = (g_err[0] + g_err[1] + g_err[2]) / denom / 3.0;
        out[NCT]     = (float)loss;
        out[NCT + 1] = expf(-ent);
    }
}

// ---------------- launch ------------------------------------------------------
extern "C" void kernel_launch(void* const* d_in, const int* in_sizes, int n_in,
                              void* d_out, int out_size) {
    const float* x = nullptr; const float* cb = nullptr; const int* m_lens = nullptr;
    for (int i = 0; i < n_in; i++) {
        if (in_sizes[i] == NCT)            x = (const float*)d_in[i];
        else if (in_sizes[i] == Kk * Cc)   cb = (const float*)d_in[i];
        else if (in_sizes[i] == Nn)        m_lens = (const int*)d_in[i];
    }
    float* out = (float*)d_out;

    const int DYN = 1024 + 4 * CHUNK_BYTES;
    cudaFuncSetAttribute(k_quantize6, cudaFuncAttributeMaxDynamicSharedMemorySize, DYN);
    cudaFuncSetAttribute(k_out2, cudaFuncAttributeMaxDynamicSharedMemorySize, OUT2_DYN);

    void* idxv = nullptr; cudaGetSymbolAddress(&idxv, g_idx);
    int* idxbase = (int*)idxv;
    void* scv = nullptr;  cudaGetSymbolAddress(&scv, g_scoreb);
    __nv_bfloat16* score = (__nv_bfloat16*)scv;

    int* idx4 = idxbase;
    int* idx2 = idxbase + Nn * 128;
    int* idx1 = idxbase + Nn * 128 + Nn * 256;
    int* idxs[3] = {idx4, idx2, idx1};

    k_prep<<<1, 1024>>>(m_lens);
    k_cbhalf<<<Kk, 128>>>(cb);
    k_cb_split<<<64, 256>>>(cb);
    {
        dim3 gb(Tt / 32, Cc / 32, Nn), tb(32, 8);
        k_transpose_in<<<gb, tb>>>(x);
    }

    const int scales[3] = {4, 2, 1};
    for (int s = 0; s < 3; s++) {
        int sc = scales[s], t = Tt / sc, M = Nn * t;
        int panels = M / 128;
        k_pool<<<panels, 256>>>(cb, m_lens, sc, t, s, idx4, idx2);
        k_quantize6<<<dim3(8, panels), 256, DYN>>>(m_lens, t, sc, score);
        k_rescore<<<M / 8, 256>>>(cb, m_lens, t, sc, idxs[s]);
    }

    {
        dim3 gb(Tt / 32, Nn);
        k_out2<<<gb, 256, OUT2_DYN>>>(cb, m_lens, idx4, idx2, idx1, out);
    }
    k_finalize<<<1, 1024>>>(out);
}